// round 13
// baseline (speedup 1.0000x reference)
#include <cuda_runtime.h>
#include <cuda_fp16.h>
#include <cstdint>

// GRU cell B=8192, I=H=1024 fp32. mma.sync fp16 m16n8k16 (fp32 accum).
// R13: zr+ht fused into ONE kernel (2048 CTAs). zr CTAs (bids 0..1023,
// bm-major) signal per-row-block flags; ht CTAs (bids 1024..2047) spin on
// their row-block flag then run. Overlaps zr/ht tails; removes the
// inter-kernel serialization. perm = R12 (coalesced transpose).

#define BB 8192
#define HH 1024
#define KK 1024

__device__ __align__(16) uint4 g_xp[BB * KK / 8];
__device__ __align__(16) uint4 g_hp[BB * KK / 8];
__device__ __align__(16) uint4 g_rhp[BB * KK / 8];
__device__ __align__(16) float g_Z[BB * HH];
__device__ __align__(16) uint2 g_Wh[6][HH * KK / 4];  // 0:Wwz 1:Wuz 2:Wwr 3:Wur 4:Wu 5:Ww
__device__ int g_flag[64];

__device__ __forceinline__ void cp_async16(void* sdst, const void* gsrc) {
    uint32_t s = (uint32_t)__cvta_generic_to_shared(sdst);
    asm volatile("cp.async.cg.shared.global [%0], [%1], 16;\n" :: "r"(s), "l"(gsrc));
}
__device__ __forceinline__ void cp_commit() { asm volatile("cp.async.commit_group;\n"); }
__device__ __forceinline__ void cp_wait1() { asm volatile("cp.async.wait_group 1;\n"); }
__device__ __forceinline__ void cp_wait0() { asm volatile("cp.async.wait_group 0;\n"); }

__device__ __forceinline__ void mma16(float c[4], const uint4& a, const uint2& b) {
    asm volatile(
        "mma.sync.aligned.m16n8k16.row.col.f32.f16.f16.f32 "
        "{%0,%1,%2,%3},{%4,%5,%6,%7},{%8,%9},{%0,%1,%2,%3};\n"
        : "+f"(c[0]), "+f"(c[1]), "+f"(c[2]), "+f"(c[3])
        : "r"(a.x), "r"(a.y), "r"(a.z), "r"(a.w), "r"(b.x), "r"(b.y));
}
__device__ __forceinline__ float sig_(float v) { return 1.0f / (1.0f + __expf(-v)); }
__device__ __forceinline__ float ftanh_(float v) {
    return 1.0f - 2.0f / (1.0f + __expf(2.0f * v));
}
__device__ __forceinline__ uint32_t h2u(float a, float b) {
    __half2 h = __floats2half2_rn(a, b);
    return *reinterpret_cast<uint32_t*>(&h);
}

// ---------------------------------------------------------------------------
// Preprocess (R12): smem-transposed, coalesced loads AND stores, 1D grid.
// ---------------------------------------------------------------------------
__global__ void __launch_bounds__(256) perm_all(
    const float* __restrict__ x, const float* __restrict__ hm,
    const float* __restrict__ w0, const float* __restrict__ w1,
    const float* __restrict__ w2, const float* __restrict__ w3,
    const float* __restrict__ w4, const float* __restrict__ w5) {
    __shared__ uint32_t sm[8 * 33 * 4];
    const int b = blockIdx.x;
    const int t = threadIdx.x;

    if (b < 8192) {
        const float* src = (b & 4096) ? hm : x;
        uint4* dst = (b & 4096) ? g_hp : g_xp;
        const int rb = (b >> 3) & 511, kbc = b & 7;
        const float4* s = reinterpret_cast<const float4*>(src + (rb * 16) * KK + kbc * 128);
        #pragma unroll
        for (int i = 0; i < 2; i++) {
            int f = t + i * 256;
            int row = f >> 5, c4 = f & 31;
            float4 v = s[row * 256 + c4];
            uint32_t p0 = h2u(v.x, v.y);
            uint32_t p1 = h2u(v.z, v.w);
            int g_ = row & 7, cr = row >> 3;
            int cp0 = c4 * 2;
            int kb0 = cp0 >> 3, j0 = cp0 & 7;
            sm[((kb0 * 33) + g_ * 4 + (j0 & 3)) * 4 + cr + 2 * (j0 >> 2)] = p0;
            int cp1 = cp0 + 1;
            int kb1 = cp1 >> 3, j1 = cp1 & 7;
            sm[((kb1 * 33) + g_ * 4 + (j1 & 3)) * 4 + cr + 2 * (j1 >> 2)] = p1;
        }
        __syncthreads();
        {
            int kb = t >> 5, lane = t & 31;
            dst[(rb * 64 + kbc * 8 + kb) * 32 + lane] =
                reinterpret_cast<const uint4*>(sm)[kb * 33 + lane];
        }
    } else {
        const int wb = b - 8192;
        const int widx = wb >> 10;
        const int bb = wb & 1023;
        const int nb = bb >> 3, kbc = bb & 7;
        const float* srcs[6] = {w0, w1, w2, w3, w4, w5};
        const float4* s = reinterpret_cast<const float4*>(srcs[widx] + (nb * 8) * KK + kbc * 128);
        {
            int f = t;
            int row = f >> 5, c4 = f & 31;
            float4 v = s[row * 256 + c4];
            uint32_t p0 = h2u(v.x, v.y);
            uint32_t p1 = h2u(v.z, v.w);
            int cp0 = c4 * 2;
            int kb0 = cp0 >> 3, j0 = cp0 & 7;
            sm[(kb0 * 33 + row * 4 + (j0 & 3)) * 2 + (j0 >> 2)] = p0;
            int cp1 = cp0 + 1;
            int kb1 = cp1 >> 3, j1 = cp1 & 7;
            sm[(kb1 * 33 + row * 4 + (j1 & 3)) * 2 + (j1 >> 2)] = p1;
        }
        __syncthreads();
        {
            int kb = t >> 5, lane = t & 31;
            g_Wh[widx][(nb * 64 + kbc * 8 + kb) * 32 + lane] =
                reinterpret_cast<const uint2*>(sm)[kb * 33 + lane];
        }
    }
}

// ---------------------------------------------------------------------------
// Fused GEMM kernel. bids [0,1024): zr role; [1024,2048): ht role.
// Both roles bm-major (bm_blk = idx>>4, bn_blk = idx&15).
// smem envelope 96KB (zr 3-stage A|Bz|Br; ht 3-stage A|B uses 72KB of it).
// ---------------------------------------------------------------------------
__global__ void __launch_bounds__(256, 2) gru_fused(const float* __restrict__ h,
                                                    float* __restrict__ out) {
    extern __shared__ uint4 sm4[];
    const int tid = threadIdx.x, wid = tid >> 5, lane = tid & 31;
    const int g = lane >> 2, tq = lane & 3;
    const int bid = blockIdx.x;

    if (bid < 1024) {
        // ================= zr role (R9 body) =================
        const int bm = (bid >> 4) * 128, bn = (bid & 15) * 64;
        const int rb0 = bm >> 4, nb0 = bn >> 3;

        auto stage = [&](int t) {
            const int seg = t >> 4, kb = (t & 15) * 4;
            const uint4* Ag = seg ? g_hp : g_xp;
            const uint4* Bz = reinterpret_cast<const uint4*>(g_Wh[seg ? 1 : 0]);
            const uint4* Br = reinterpret_cast<const uint4*>(g_Wh[seg ? 3 : 2]);
            uint4* dst = &sm4[(t % 3) * 2048];
            #pragma unroll
            for (int i = 0; i < 4; i++) {
                int c = tid + i * 256, rbl = c >> 7, rem = c & 127;
                cp_async16(&dst[c], &Ag[((rb0 + rbl) * 64 + kb) * 32 + rem]);
            }
            #pragma unroll
            for (int i = 0; i < 2; i++) {
                int c = tid + i * 256, nbl = c >> 6, rem = c & 63;
                int so = ((nb0 + nbl) * 64 + kb) * 16 + rem;
                cp_async16(&dst[1024 + c], &Bz[so]);
                cp_async16(&dst[1536 + c], &Br[so]);
            }
            cp_commit();
        };

        float accZ[2][4][4] = {}, accR[2][4][4] = {};
        stage(0);
        stage(1);

        const int r0 = (wid & 3) * 2, nbl = (wid >> 2) * 4;
        for (int t = 0; t < 32; t++) {
            if (t + 2 < 32) cp_wait1(); else cp_wait0();
            __syncthreads();
            if (t + 2 < 32) stage(t + 2);
            const uint4* A_ = &sm4[(t % 3) * 2048];
            const uint2* Bz_ = reinterpret_cast<const uint2*>(&A_[1024]);
            const uint2* Br_ = reinterpret_cast<const uint2*>(&A_[1536]);
            #pragma unroll
            for (int kk = 0; kk < 4; kk++) {
                uint4 a0 = A_[(r0 * 4 + kk) * 32 + lane];
                uint4 a1 = A_[((r0 + 1) * 4 + kk) * 32 + lane];
                #pragma unroll
                for (int nt = 0; nt < 4; nt++) {
                    uint2 bz = Bz_[(nbl + nt) * 128 + kk * 32 + lane];
                    uint2 br = Br_[(nbl + nt) * 128 + kk * 32 + lane];
                    mma16(accZ[0][nt], a0, bz);
                    mma16(accZ[1][nt], a1, bz);
                    mma16(accR[0][nt], a0, br);
                    mma16(accR[1][nt], a1, br);
                }
            }
        }

        uint32_t* rhp32 = reinterpret_cast<uint32_t*>(g_rhp);
        const int wm = (wid & 3) * 32, wn = (wid >> 2) * 32;
        #pragma unroll
        for (int mt = 0; mt < 2; mt++) {
            const int rbase = bm + wm + mt * 16;
            #pragma unroll
            for (int nt = 0; nt < 4; nt++) {
                const int colb = bn + wn + nt * 8 + tq * 2;
                const int kb = ((bn + wn) >> 4) + (nt >> 1);
                #pragma unroll
                for (int half = 0; half < 2; half++) {
                    const int row = rbase + half * 8 + g;
                    const int idx = row * HH + colb;
                    float2 hv = *reinterpret_cast<const float2*>(&h[idx]);
                    float2 zo;
                    zo.x = sig_(accZ[mt][nt][half * 2]);
                    zo.y = sig_(accZ[mt][nt][half * 2 + 1]);
                    *reinterpret_cast<float2*>(&g_Z[idx]) = zo;
                    float rh0 = sig_(accR[mt][nt][half * 2]) * hv.x;
                    float rh1 = sig_(accR[mt][nt][half * 2 + 1]) * hv.y;
                    const int rbm = (rbase >> 4);
                    const int regidx = half + 2 * (nt & 1);
                    rhp32[((rbm * 64 + kb) * 32 + lane) * 4 + regidx] = h2u(rh0, rh1);
                }
            }
        }

        // release: all threads fence, then one arrival per CTA
        __threadfence();
        __syncthreads();
        if (tid == 0) atomicAdd(&g_flag[bid >> 4], 1);
    } else {
        // ================= ht role (R9 body) =================
        const int idx0 = bid - 1024;
        const int bm = (idx0 >> 4) * 128, bn = (idx0 & 15) * 64;
        const int mblk = idx0 >> 4;

        // acquire: wait for all 16 zr CTAs of this row block
        if (tid == 0) {
            int v;
            do {
                asm volatile("ld.global.cg.s32 %0, [%1];" : "=r"(v) : "l"(&g_flag[mblk]));
            } while (v < 16);
        }
        __syncthreads();
        __threadfence();

        const int rb0 = bm >> 4, nb0 = bn >> 3;
        const int mrow = wid & 3, ncol = wid >> 2;

        auto stage = [&](int t) {
            const int seg = t >> 4, kb0 = (t & 15) * 4;
            const uint4* Ag = seg ? g_xp : g_rhp;
            const uint4* Bg = reinterpret_cast<const uint4*>(g_Wh[seg ? 5 : 4]);
            uint4* dst = &sm4[(t % 3) * 1536];
            #pragma unroll
            for (int i = 0; i < 4; i++) {
                int c = tid + i * 256, rbl = c >> 7, rem = c & 127;
                cp_async16(&dst[c], &Ag[((rb0 + rbl) * 64 + kb0) * 32 + rem]);
            }
            #pragma unroll
            for (int i = 0; i < 2; i++) {
                int c = tid + i * 256, nbl = c >> 6, rem = c & 63;
                cp_async16(&dst[1024 + c], &Bg[((nb0 + nbl) * 64 + kb0) * 16 + rem]);
            }
            cp_commit();
        };

        float acc[2][4][4] = {};
        stage(0);
        stage(1);

        for (int t = 0; t < 32; t++) {
            if (t + 2 < 32) cp_wait1(); else cp_wait0();
            __syncthreads();
            if (t + 2 < 32) stage(t + 2);
            const uint4* A_ = &sm4[(t % 3) * 1536];
            const uint2* B_ = reinterpret_cast<const uint2*>(&A_[1024]);
            #pragma unroll
            for (int kk = 0; kk < 4; kk++) {
                uint4 a0 = A_[((mrow * 2 + 0) * 4 + kk) * 32 + lane];
                uint4 a1 = A_[((mrow * 2 + 1) * 4 + kk) * 32 + lane];
                #pragma unroll
                for (int n = 0; n < 4; n++) {
                    uint2 b = B_[((ncol * 4 + n) * 4 + kk) * 32 + lane];
                    mma16(acc[0][n], a0, b);
                    mma16(acc[1][n], a1, b);
                }
            }
        }

        #pragma unroll
        for (int r = 0; r < 2; r++) {
            const int rowbase = bm + mrow * 32 + r * 16;
            #pragma unroll
            for (int n = 0; n < 4; n++) {
                const int col = bn + ncol * 32 + n * 8 + tq * 2;
                #pragma unroll
                for (int half = 0; half < 2; half++) {
                    const int oidx = (rowbase + half * 8 + g) * HH + col;
                    float2 hv = *reinterpret_cast<const float2*>(&h[oidx]);
                    float2 zv = *reinterpret_cast<const float2*>(&g_Z[oidx]);
                    float2 ov;
                    ov.x = zv.x * hv.x + (1.0f - zv.x) * ftanh_(acc[r][n][half * 2]);
                    ov.y = zv.y * hv.y + (1.0f - zv.y) * ftanh_(acc[r][n][half * 2 + 1]);
                    *reinterpret_cast<float2*>(&out[oidx]) = ov;
                }
            }
        }
    }
}

// ---------------------------------------------------------------------------
extern "C" void kernel_launch(void* const* d_in, const int* in_sizes, int n_in,
                              void* d_out, int out_size) {
    const float* x   = (const float*)d_in[0];
    const float* h   = (const float*)d_in[1];
    const float* Wwz = (const float*)d_in[2];
    const float* Wuz = (const float*)d_in[3];
    const float* Wwr = (const float*)d_in[4];
    const float* Wur = (const float*)d_in[5];
    const float* Wu  = (const float*)d_in[6];
    const float* Ww  = (const float*)d_in[7];
    float* out = (float*)d_out;

    const int smem = 6144 * 16;   // 96 KB
    cudaFuncSetAttribute(gru_fused, cudaFuncAttributeMaxDynamicSharedMemorySize, smem);

    void* flagp = nullptr;
    cudaGetSymbolAddress(&flagp, g_flag);
    cudaMemsetAsync(flagp, 0, 64 * sizeof(int));

    perm_all<<<14336, 256>>>(x, h, Wwz, Wuz, Wwr, Wur, Wu, Ww);
    gru_fused<<<2048, 256, smem>>>(h, out);
}

// round 14
// speedup vs baseline: 1.0363x; 1.0363x over previous
#include <cuda_runtime.h>
#include <cuda_fp16.h>
#include <cstdint>

// GRU cell B=8192, I=H=1024 fp32. mma.sync fp16 m16n8k16 (fp32 accum).
// R14: fused zr+ht with occupancy-matched bodies. Both roles tuned for the
// 2-CTA/SM envelope (64KB smem, ~125 regs): zr = R7 zr (warp 32x32 dual);
// ht = R7 ht (block 128x128, warp 64x32, measured best at 2 CTA/SM).
// Flags/spin scheme validated in R13. perm = R12.

#define BB 8192
#define HH 1024
#define KK 1024

__device__ __align__(16) uint4 g_xp[BB * KK / 8];
__device__ __align__(16) uint4 g_hp[BB * KK / 8];
__device__ __align__(16) uint4 g_rhp[BB * KK / 8];
__device__ __align__(16) float g_Z[BB * HH];
__device__ __align__(16) uint2 g_Wh[6][HH * KK / 4];  // 0:Wwz 1:Wuz 2:Wwr 3:Wur 4:Wu 5:Ww
__device__ int g_flag[64];

__device__ __forceinline__ void cp_async16(void* sdst, const void* gsrc) {
    uint32_t s = (uint32_t)__cvta_generic_to_shared(sdst);
    asm volatile("cp.async.cg.shared.global [%0], [%1], 16;\n" :: "r"(s), "l"(gsrc));
}
__device__ __forceinline__ void cp_commit() { asm volatile("cp.async.commit_group;\n"); }
__device__ __forceinline__ void cp_wait_all() { asm volatile("cp.async.wait_group 0;\n"); }

__device__ __forceinline__ void mma16(float c[4], const uint4& a, const uint2& b) {
    asm volatile(
        "mma.sync.aligned.m16n8k16.row.col.f32.f16.f16.f32 "
        "{%0,%1,%2,%3},{%4,%5,%6,%7},{%8,%9},{%0,%1,%2,%3};\n"
        : "+f"(c[0]), "+f"(c[1]), "+f"(c[2]), "+f"(c[3])
        : "r"(a.x), "r"(a.y), "r"(a.z), "r"(a.w), "r"(b.x), "r"(b.y));
}
__device__ __forceinline__ float sig_(float v) { return 1.0f / (1.0f + __expf(-v)); }
__device__ __forceinline__ float ftanh_(float v) {
    return 1.0f - 2.0f / (1.0f + __expf(2.0f * v));
}
__device__ __forceinline__ uint32_t h2u(float a, float b) {
    __half2 h = __floats2half2_rn(a, b);
    return *reinterpret_cast<uint32_t*>(&h);
}

// ---------------------------------------------------------------------------
// Preprocess (R12): smem-transposed, coalesced loads AND stores, 1D grid.
// ---------------------------------------------------------------------------
__global__ void __launch_bounds__(256) perm_all(
    const float* __restrict__ x, const float* __restrict__ hm,
    const float* __restrict__ w0, const float* __restrict__ w1,
    const float* __restrict__ w2, const float* __restrict__ w3,
    const float* __restrict__ w4, const float* __restrict__ w5) {
    __shared__ uint32_t sm[8 * 33 * 4];
    const int b = blockIdx.x;
    const int t = threadIdx.x;

    if (b < 8192) {
        const float* src = (b & 4096) ? hm : x;
        uint4* dst = (b & 4096) ? g_hp : g_xp;
        const int rb = (b >> 3) & 511, kbc = b & 7;
        const float4* s = reinterpret_cast<const float4*>(src + (rb * 16) * KK + kbc * 128);
        #pragma unroll
        for (int i = 0; i < 2; i++) {
            int f = t + i * 256;
            int row = f >> 5, c4 = f & 31;
            float4 v = s[row * 256 + c4];
            uint32_t p0 = h2u(v.x, v.y);
            uint32_t p1 = h2u(v.z, v.w);
            int g_ = row & 7, cr = row >> 3;
            int cp0 = c4 * 2;
            int kb0 = cp0 >> 3, j0 = cp0 & 7;
            sm[((kb0 * 33) + g_ * 4 + (j0 & 3)) * 4 + cr + 2 * (j0 >> 2)] = p0;
            int cp1 = cp0 + 1;
            int kb1 = cp1 >> 3, j1 = cp1 & 7;
            sm[((kb1 * 33) + g_ * 4 + (j1 & 3)) * 4 + cr + 2 * (j1 >> 2)] = p1;
        }
        __syncthreads();
        {
            int kb = t >> 5, lane = t & 31;
            dst[(rb * 64 + kbc * 8 + kb) * 32 + lane] =
                reinterpret_cast<const uint4*>(sm)[kb * 33 + lane];
        }
    } else {
        const int wb = b - 8192;
        const int widx = wb >> 10;
        const int bb = wb & 1023;
        const int nb = bb >> 3, kbc = bb & 7;
        const float* srcs[6] = {w0, w1, w2, w3, w4, w5};
        const float4* s = reinterpret_cast<const float4*>(srcs[widx] + (nb * 8) * KK + kbc * 128);
        {
            int f = t;
            int row = f >> 5, c4 = f & 31;
            float4 v = s[row * 256 + c4];
            uint32_t p0 = h2u(v.x, v.y);
            uint32_t p1 = h2u(v.z, v.w);
            int cp0 = c4 * 2;
            int kb0 = cp0 >> 3, j0 = cp0 & 7;
            sm[(kb0 * 33 + row * 4 + (j0 & 3)) * 2 + (j0 >> 2)] = p0;
            int cp1 = cp0 + 1;
            int kb1 = cp1 >> 3, j1 = cp1 & 7;
            sm[(kb1 * 33 + row * 4 + (j1 & 3)) * 2 + (j1 >> 2)] = p1;
        }
        __syncthreads();
        {
            int kb = t >> 5, lane = t & 31;
            g_Wh[widx][(nb * 64 + kbc * 8 + kb) * 32 + lane] =
                reinterpret_cast<const uint2*>(sm)[kb * 33 + lane];
        }
    }
}

// ---------------------------------------------------------------------------
// Fused GEMM kernel, 1536 CTAs, 64KB smem, 2 CTAs/SM.
//  bids [0,1024):    zr role, block 128x64, bm=(bid>>4)*128, bn=(bid&15)*64
//  bids [1024,1536): ht role, block 128x128, bm=(idx>>3)*128, bn=(idx&7)*128
// ---------------------------------------------------------------------------
__global__ void __launch_bounds__(256, 2) gru_fused(const float* __restrict__ h,
                                                    float* __restrict__ out) {
    extern __shared__ uint4 sm4[];
    const int tid = threadIdx.x, wid = tid >> 5, lane = tid & 31;
    const int g = lane >> 2, tq = lane & 3;
    const int bid = blockIdx.x;

    if (bid < 1024) {
        // ================= zr role (R7 zr body, 2-stage 64KB) =================
        const int bm = (bid >> 4) * 128, bn = (bid & 15) * 64;
        const int rb0 = bm >> 4, nb0 = bn >> 3;

        auto stage = [&](int t, int buf) {
            const int seg = t >> 4, kb = (t & 15) * 4;
            const uint4* Ag = seg ? g_hp : g_xp;
            const uint4* Bz = reinterpret_cast<const uint4*>(g_Wh[seg ? 1 : 0]);
            const uint4* Br = reinterpret_cast<const uint4*>(g_Wh[seg ? 3 : 2]);
            #pragma unroll
            for (int i = 0; i < 4; i++) {
                int c = tid + i * 256, rbl = c >> 7, rem = c & 127;
                cp_async16(&sm4[buf * 1024 + rbl * 128 + rem],
                           &Ag[((rb0 + rbl) * 64 + kb) * 32 + rem]);
            }
            #pragma unroll
            for (int i = 0; i < 2; i++) {
                int c = tid + i * 256, nbl = c >> 6, rem = c & 63;
                int so = ((nb0 + nbl) * 64 + kb) * 16 + rem;
                cp_async16(&sm4[2048 + buf * 512 + nbl * 64 + rem], &Bz[so]);
                cp_async16(&sm4[3072 + buf * 512 + nbl * 64 + rem], &Br[so]);
            }
            cp_commit();
        };

        float accZ[2][4][4] = {}, accR[2][4][4] = {};
        stage(0, 0);

        const int r0 = (wid & 3) * 2, nbl = (wid >> 2) * 4;
        for (int t = 0; t < 32; t++) {
            cp_wait_all();
            __syncthreads();
            if (t + 1 < 32) stage(t + 1, (t + 1) & 1);
            const int buf = t & 1;
            const uint4* A_ = &sm4[buf * 1024];
            const uint2* Bz_ = reinterpret_cast<const uint2*>(&sm4[2048 + buf * 512]);
            const uint2* Br_ = reinterpret_cast<const uint2*>(&sm4[3072 + buf * 512]);
            #pragma unroll
            for (int kk = 0; kk < 4; kk++) {
                uint4 a0 = A_[(r0 * 4 + kk) * 32 + lane];
                uint4 a1 = A_[((r0 + 1) * 4 + kk) * 32 + lane];
                #pragma unroll
                for (int nt = 0; nt < 4; nt++) {
                    uint2 bz = Bz_[(nbl + nt) * 128 + kk * 32 + lane];
                    uint2 br = Br_[(nbl + nt) * 128 + kk * 32 + lane];
                    mma16(accZ[0][nt], a0, bz);
                    mma16(accZ[1][nt], a1, bz);
                    mma16(accR[0][nt], a0, br);
                    mma16(accR[1][nt], a1, br);
                }
            }
            __syncthreads();
        }

        uint32_t* rhp32 = reinterpret_cast<uint32_t*>(g_rhp);
        const int wm = (wid & 3) * 32, wn = (wid >> 2) * 32;
        #pragma unroll
        for (int mt = 0; mt < 2; mt++) {
            const int rbase = bm + wm + mt * 16;
            #pragma unroll
            for (int nt = 0; nt < 4; nt++) {
                const int colb = bn + wn + nt * 8 + tq * 2;
                const int kb = ((bn + wn) >> 4) + (nt >> 1);
                #pragma unroll
                for (int half = 0; half < 2; half++) {
                    const int row = rbase + half * 8 + g;
                    const int idx = row * HH + colb;
                    float2 hv = *reinterpret_cast<const float2*>(&h[idx]);
                    float2 zo;
                    zo.x = sig_(accZ[mt][nt][half * 2]);
                    zo.y = sig_(accZ[mt][nt][half * 2 + 1]);
                    *reinterpret_cast<float2*>(&g_Z[idx]) = zo;
                    float rh0 = sig_(accR[mt][nt][half * 2]) * hv.x;
                    float rh1 = sig_(accR[mt][nt][half * 2 + 1]) * hv.y;
                    const int rbm = (rbase >> 4);
                    const int regidx = half + 2 * (nt & 1);
                    rhp32[((rbm * 64 + kb) * 32 + lane) * 4 + regidx] = h2u(rh0, rh1);
                }
            }
        }

        __threadfence();
        __syncthreads();
        if (tid == 0) atomicAdd(&g_flag[bid >> 4], 1);
    } else {
        // ================= ht role (R7 ht body: 128x128, warp 64x32) ==========
        const int idx0 = bid - 1024;
        const int bm = (idx0 >> 3) * 128, bn = (idx0 & 7) * 128;
        const int mblk = idx0 >> 3;

        if (tid == 0) {
            int v;
            do {
                asm volatile("ld.global.cg.s32 %0, [%1];" : "=r"(v) : "l"(&g_flag[mblk]));
            } while (v < 16);
        }
        __syncthreads();
        __threadfence();

        const int rb0 = bm >> 4, nb0 = bn >> 3;
        const int mrow = wid & 1, ncol = wid >> 1;   // 2 x 4 warps, warp 64x32

        auto stage = [&](int t, int buf) {
            const int seg = t >> 4, kb0 = (t & 15) * 4;
            const uint4* Ag = seg ? g_xp : g_rhp;
            const uint4* Bg = reinterpret_cast<const uint4*>(g_Wh[seg ? 5 : 4]);
            uint4* dst = &sm4[buf * 2048];
            #pragma unroll
            for (int i = 0; i < 4; i++) {
                int c = tid + i * 256, rbl = c >> 7, rem = c & 127;
                cp_async16(&dst[c], &Ag[((rb0 + rbl) * 64 + kb0) * 32 + rem]);
            }
            #pragma unroll
            for (int i = 0; i < 4; i++) {
                int c = tid + i * 256, nb = c >> 6, rem = c & 63;
                cp_async16(&dst[1024 + c], &Bg[((nb0 + nb) * 64 + kb0) * 16 + rem]);
            }
            cp_commit();
        };

        float acc[4][4][4] = {};
        stage(0, 0);

        for (int t = 0; t < 32; t++) {
            cp_wait_all();
            __syncthreads();
            if (t + 1 < 32) stage(t + 1, (t + 1) & 1);
            const uint4* A_ = &sm4[(t & 1) * 2048];
            const uint2* B_ = reinterpret_cast<const uint2*>(&sm4[(t & 1) * 2048 + 1024]);
            #pragma unroll
            for (int kk = 0; kk < 4; kk++) {
                uint4 a[4];
                #pragma unroll
                for (int r = 0; r < 4; r++)
                    a[r] = A_[((mrow * 4 + r) * 4 + kk) * 32 + lane];
                #pragma unroll
                for (int n = 0; n < 4; n++) {
                    uint2 b = B_[((ncol * 4 + n) * 4 + kk) * 32 + lane];
                    #pragma unroll
                    for (int r = 0; r < 4; r++)
                        mma16(acc[r][n], a[r], b);
                }
            }
            __syncthreads();
        }

        #pragma unroll
        for (int r = 0; r < 4; r++) {
            const int rowbase = bm + mrow * 64 + r * 16;
            #pragma unroll
            for (int n = 0; n < 4; n++) {
                const int col = bn + ncol * 32 + n * 8 + tq * 2;
                #pragma unroll
                for (int half = 0; half < 2; half++) {
                    const int oidx = (rowbase + half * 8 + g) * HH + col;
                    float2 hv = *reinterpret_cast<const float2*>(&h[oidx]);
                    float2 zv = *reinterpret_cast<const float2*>(&g_Z[oidx]);
                    float2 ov;
                    ov.x = zv.x * hv.x + (1.0f - zv.x) * ftanh_(acc[r][n][half * 2]);
                    ov.y = zv.y * hv.y + (1.0f - zv.y) * ftanh_(acc[r][n][half * 2 + 1]);
                    *reinterpret_cast<float2*>(&out[oidx]) = ov;
                }
            }
        }
    }
}

// ---------------------------------------------------------------------------
extern "C" void kernel_launch(void* const* d_in, const int* in_sizes, int n_in,
                              void* d_out, int out_size) {
    const float* x   = (const float*)d_in[0];
    const float* h   = (const float*)d_in[1];
    const float* Wwz = (const float*)d_in[2];
    const float* Wuz = (const float*)d_in[3];
    const float* Wwr = (const float*)d_in[4];
    const float* Wur = (const float*)d_in[5];
    const float* Wu  = (const float*)d_in[6];
    const float* Ww  = (const float*)d_in[7];
    float* out = (float*)d_out;

    const int smem = 4096 * 16;   // 64 KB (both roles)
    cudaFuncSetAttribute(gru_fused, cudaFuncAttributeMaxDynamicSharedMemorySize, smem);

    void* flagp = nullptr;
    cudaGetSymbolAddress(&flagp, g_flag);
    cudaMemsetAsync(flagp, 0, 64 * sizeof(int));

    perm_all<<<14336, 256>>>(x, h, Wwz, Wuz, Wwr, Wur, Wu, Ww);
    gru_fused<<<1536, 256, smem>>>(h, out);
}